// round 1
// baseline (speedup 1.0000x reference)
#include <cuda_runtime.h>
#include <math.h>

#define Hh 2048
#define Wd 2048
#define MASKM 2047
#define Kk 16
#define Pp 15

// scratch (static device globals — no allocation)
__device__ float g_rowsum[Hh * Wd];
__device__ float g_win[Hh * Wd];
__device__ int2  g_off[Kk];
__device__ float g_C;

// ---------------------------------------------------------------------------
// Kernel 0: reduce patterns -> constant C; compute normalized shift offsets
// ---------------------------------------------------------------------------
__global__ void k_prep(const float* __restrict__ patterns,
                       const float* __restrict__ vectors) {
    __shared__ float red[256];
    int t = threadIdx.x;
    float s = 0.f;
    for (int i = t; i < Kk * Pp * Pp; i += 256) s += patterns[i];
    red[t] = s;
    __syncthreads();
    for (int off = 128; off > 0; off >>= 1) {
        if (t < off) red[t] += red[t + off];
        __syncthreads();
    }
    if (t == 0) {
        float tot = red[0];
        g_C = ((float)Kk - tot / (float)(Pp * Pp)) / (float)(Kk - 1);
    }
    if (t < Kk) {
        int oy = (int)floorf(vectors[2 * t]);
        int ox = (int)floorf(vectors[2 * t + 1]);
        int ny = oy & MASKM; if (ny >= 1024) ny -= 2048;
        int nx = ox & MASKM; if (nx >= 1024) nx -= 2048;
        g_off[t] = make_int2(ny, nx);
    }
}

// ---------------------------------------------------------------------------
// Kernel A: horizontal sliding 15-sum.
// rowsum[i][j] = sum_{t=1..15} img[i][j-t]  (zero for j-t < 0)
// One block per row, 256 threads, 8 outputs/thread.
// ---------------------------------------------------------------------------
__global__ void k_rowsum(const float* __restrict__ img) {
    int i = blockIdx.x;
    int j0 = threadIdx.x * 8;
    const float* row = img + (size_t)i * Wd;

    float v[24];  // v[x] = img[i][j0-16+x]
    if (j0 >= 16) {
        const float4* p = (const float4*)(row + j0 - 16);
        #pragma unroll
        for (int q = 0; q < 6; q++) {
            float4 f = __ldg(p + q);
            v[4 * q + 0] = f.x; v[4 * q + 1] = f.y;
            v[4 * q + 2] = f.z; v[4 * q + 3] = f.w;
        }
    } else {
        #pragma unroll
        for (int x = 0; x < 24; x++) {
            int c = j0 - 16 + x;
            v[x] = (c >= 0) ? __ldg(row + c) : 0.f;
        }
    }

    float s = 0.f;
    #pragma unroll
    for (int x = 1; x <= 15; x++) s += v[x];
    float o[8];
    o[0] = s;
    #pragma unroll
    for (int c = 1; c < 8; c++) { s += v[15 + c] - v[c]; o[c] = s; }

    float4* outp = (float4*)(g_rowsum + (size_t)i * Wd + j0);
    outp[0] = make_float4(o[0], o[1], o[2], o[3]);
    outp[1] = make_float4(o[4], o[5], o[6], o[7]);
}

// ---------------------------------------------------------------------------
// Kernel B: vertical sliding 15-sum.
// win[i][j] = sum_{t=1..15} rowsum[i-t][j]   (zero for i-t < 0)
// Each thread: 4 columns (float4) x 16 rows, register ring of 15 float4.
// blockDim = 128, grid = (4, 128).
// ---------------------------------------------------------------------------
__global__ void k_colsum() {
    int c0 = 4 * (blockIdx.x * blockDim.x + threadIdx.x);
    int i0 = blockIdx.y * 16;

    float4 buf[15];
    float4 s = make_float4(0.f, 0.f, 0.f, 0.f);
    #pragma unroll
    for (int t = 0; t < 15; t++) {
        int r = i0 - 15 + t;
        float4 f = make_float4(0.f, 0.f, 0.f, 0.f);
        if (r >= 0) f = *(const float4*)(g_rowsum + (size_t)r * Wd + c0);
        buf[t] = f;
        s.x += f.x; s.y += f.y; s.z += f.z; s.w += f.w;
    }
    #pragma unroll
    for (int r = 0; r < 16; r++) {
        *(float4*)(g_win + (size_t)(i0 + r) * Wd + c0) = s;
        if (r < 15) {
            float4 f = *(const float4*)(g_rowsum + (size_t)(i0 + r) * Wd + c0);
            s.x += f.x - buf[r].x;
            s.y += f.y - buf[r].y;
            s.z += f.z - buf[r].z;
            s.w += f.w - buf[r].w;
            buf[r] = f;
        }
    }
}

// ---------------------------------------------------------------------------
// Kernel C: out[i,j] = C + (1/3375) * sum_k win[(i-oy_k)&2047][(j-ox_k)&2047]
// 128x64 output tile/block. Stage 80x144 halo tile of win in SMEM (wrap-safe
// staging). Fast path for |shift|<=8; uniform global-gather fallback.
// blockDim = 256, grid = (16, 32).
// ---------------------------------------------------------------------------
__global__ void k_gather(float* __restrict__ out) {
    __shared__ float tile[80][144];
    __shared__ int2 soff[Kk];
    __shared__ float sC;

    int t = threadIdx.x;
    int j0 = blockIdx.x * 128;
    int i0 = blockIdx.y * 64;

    if (t < Kk) soff[t] = g_off[t];
    if (t == 0) sC = g_C;

    for (int idx = t; idx < 80 * 144; idx += 256) {
        int u = idx / 144, v = idx - u * 144;
        int gr = (i0 - 8 + u) & MASKM;
        int gc = (j0 - 8 + v) & MASKM;
        tile[u][v] = __ldg(g_win + (size_t)gr * Wd + gc);
    }
    __syncthreads();

    int tx = t & 127;          // column within tile
    int r0 = (t >> 7) * 32;    // 0 or 32: row block

    float acc[32];
    #pragma unroll
    for (int rr = 0; rr < 32; rr++) acc[rr] = 0.f;

    #pragma unroll
    for (int k = 0; k < Kk; k++) {
        int sy = soff[k].x, sx = soff[k].y;
        if (sy >= -8 && sy <= 8 && sx >= -8 && sx <= 8) {
            int v  = tx + 8 - sx;
            int ub = r0 + 8 - sy;
            #pragma unroll
            for (int rr = 0; rr < 32; rr++) acc[rr] += tile[ub + rr][v];
        } else {
            int gc = (j0 + tx - sx) & MASKM;
            #pragma unroll
            for (int rr = 0; rr < 32; rr++) {
                int gr = (i0 + r0 + rr - sy) & MASKM;
                acc[rr] += __ldg(g_win + (size_t)gr * Wd + gc);
            }
        }
    }

    const float scale = 1.0f / 3375.0f;
    float c = sC;
    #pragma unroll
    for (int rr = 0; rr < 32; rr++)
        out[(size_t)(i0 + r0 + rr) * Wd + j0 + tx] = c + scale * acc[rr];
}

// ---------------------------------------------------------------------------
extern "C" void kernel_launch(void* const* d_in, const int* in_sizes, int n_in,
                              void* d_out, int out_size) {
    const float* x        = (const float*)d_in[0];  // (1,1,2048,2048)
    const float* patterns = (const float*)d_in[1];  // (16,15,15)
    const float* vectors  = (const float*)d_in[2];  // (16,2)
    float* out = (float*)d_out;                     // (2048,2048)

    k_prep<<<1, 256>>>(patterns, vectors);
    k_rowsum<<<Hh, 256>>>(x);
    k_colsum<<<dim3(4, 128), 128>>>();
    k_gather<<<dim3(16, 32), 256>>>(out);
}